// round 7
// baseline (speedup 1.0000x reference)
#include <cuda_runtime.h>
#include <math.h>

// Problem dims (fixed by setup_inputs)
#define BB   8
#define HH   512
#define WW   512
#define HP   128
#define WP   128
#define CF   256
#define SP   (HP*WP)            // 16384 spatial per plane
#define NF   (BB*CF*SP)         // 33554432 F_in elements
#define NV4  (NF/4)             // 8388608 float4s
#define GRID 592                // 148 SMs x 4 blocks -> all resident
#define TPB  256

// Phase-1 tickets: [0,48) img pool, [48,64) distance transform, [64,1088) F sweep
#define NT_IMG  48
#define NT_DT   16
#define NT_F    1024
#define NT1     (NT_IMG + NT_DT + NT_F)
#define F_CHUNK 8192            // float4 per F ticket (32 per thread, 128KB)
// Phase-3: 1024 units (b, cg of 32ch, chunk of 1024px), walked in reverse
#define NT3     1024

// Device scratch (no allocations allowed). Ticket counters are reset inside
// the barrier each replay; g_bar/g_rel are monotonic -> replay-safe.
__device__ double g_ps[GRID];
__device__ double g_pq[GRID];
__device__ float  g_img_ds[BB*3*SP];   // 4x4 avg-pooled img (1.5 MiB)
__device__ float  g_dh[BB*SP];         // distance-valued D_h
__device__ float4 g_wpack[2*CF];       // [2c]={gw0,gw1,gw2,gb}, [2c+1]={bw..}
__device__ unsigned int g_bar;         // arrival count (monotonic)
__device__ unsigned int g_rel;         // release epoch (monotonic)
__device__ unsigned int g_t1;          // phase-1 ticket counter
__device__ unsigned int g_t3;          // phase-3 ticket counter

// ---------------------------------------------------------------- grid barrier + counter reset
__device__ __forceinline__ void grid_barrier_reset() {
    __syncthreads();
    if (threadIdx.x == 0) {
        __threadfence();
        unsigned int old = atomicAdd(&g_bar, 1u);
        unsigned int epoch = old / GRID;
        if (old % GRID == GRID - 1) {
            g_t1 = 0u;
            g_t3 = 0u;
            __threadfence();
            atomicAdd(&g_rel, 1u);
        } else {
            while (*((volatile unsigned int*)&g_rel) < epoch + 1u) __nanosleep(32);
        }
        __threadfence();
    }
    __syncthreads();
}

// ---------------------------------------------------------------- on-the-fly 4x4 max-pool of raw mask
__device__ __forceinline__ float pooled_max(const float* __restrict__ mb, int h, int w) {
    const float* p = mb + (size_t)(h * 4) * WW + w * 4;
    float mx = 0.f;
    #pragma unroll
    for (int r = 0; r < 4; r++) {
        float4 v = __ldg((const float4*)(p + (size_t)r * WW));
        mx = fmaxf(mx, fmaxf(fmaxf(v.x, v.y), fmaxf(v.z, v.w)));
    }
    return mx;
}

// ---------------------------------------------------------------- the whole problem, one kernel
__global__ void __launch_bounds__(TPB, 4)
fused_kernel(const float4* __restrict__ F,
             const float*  __restrict__ img,
             const float*  __restrict__ mask,
             const float*  __restrict__ gw, const float* __restrict__ gB,
             const float*  __restrict__ bw, const float* __restrict__ bB,
             float4* __restrict__ out) {
    __shared__ double s_s[TPB];
    __shared__ double s_q[TPB];
    __shared__ float  s_stats[2];
    __shared__ unsigned int s_t;
    const int tid = threadIdx.x;
    const int bid = blockIdx.x;

    // Weight packing (tiny, static: block 0)
    if (bid == 0 && tid < CF) {
        g_wpack[2*tid]     = make_float4(gw[3*tid], gw[3*tid+1], gw[3*tid+2], gB[tid]);
        g_wpack[2*tid + 1] = make_float4(bw[3*tid], bw[3*tid+1], bw[3*tid+2], bB[tid]);
    }

    // ---------------- Phase 1: dynamic tickets, THREAD-LOCAL accumulation.
    // Ticket order over time: img pool, mask DT, then F sweep front-to-back
    // (fills L2 with F's tail for the reverse-order epilogue).
    double ds = 0.0, dq = 0.0;          // per-thread F partials (registers)
    for (;;) {
        __syncthreads();
        if (tid == 0) s_t = atomicAdd(&g_t1, 1u);
        __syncthreads();
        unsigned int t = s_t;
        if (t >= NT1) break;

        if (t < NT_IMG) {
            // img 4x4 avg-pool: 8192 outputs per ticket, 32 per thread
            int base = t * 8192;
            #pragma unroll 4
            for (int k = 0; k < 32; k++) {
                int idx = base + k * TPB + tid;
                int wp = idx & 127;
                int hp = (idx >> 7) & 127;
                int ch = (idx >> 14) % 3;
                int b  = idx / (3 * SP);
                const float* p = img + ((size_t)(b * 3 + ch) * HH + hp * 4) * WW + wp * 4;
                float s = 0.f;
                #pragma unroll
                for (int r = 0; r < 4; r++) {
                    float4 v = __ldcs((const float4*)(p + (size_t)r * WW));
                    s += (v.x + v.y) + (v.z + v.w);
                }
                g_img_ds[idx] = s * (1.f / 16.f);
            }
        } else if (t < NT_IMG + NT_DT) {
            // Chebyshev DT from raw mask: 5 iters of (3x3 dilate -> 2^-i on
            // newly reached) == d = Cheb dist to nearest pooled-1, val = 2^-d.
            int base = (t - NT_IMG) * 8192;
            for (int k = 0; k < 32; k++) {
                int gt = base + k * TPB + tid;
                int b   = gt >> 14;
                int rem = gt & 16383;
                int h = rem >> 7, w = rem & 127;
                const float* mb = mask + (size_t)b * 3 * HH * WW;   // channel 0
                float val;
                if (pooled_max(mb, h, w) > 0.5f) {
                    val = 1.f;                                       // dominant path
                } else {
                    val = 0.f;
                    for (int d = 1; d <= 5; d++) {
                        bool hit = false;
                        int y0 = h - d, y1 = h + d;
                        int xlo = w - d < 0 ? 0 : w - d;
                        int xhi = w + d > WP - 1 ? WP - 1 : w + d;
                        if (y0 >= 0) for (int x = xlo; x <= xhi; x++) hit |= pooled_max(mb, y0, x) > 0.5f;
                        if (y1 < HP) for (int x = xlo; x <= xhi; x++) hit |= pooled_max(mb, y1, x) > 0.5f;
                        int ylo = h - d + 1 < 0 ? 0 : h - d + 1;
                        int yhi = h + d - 1 > HP - 1 ? HP - 1 : h + d - 1;
                        if (w - d >= 0) for (int y = ylo; y <= yhi; y++) hit |= pooled_max(mb, y, w - d) > 0.5f;
                        if (w + d < WP) for (int y = ylo; y <= yhi; y++) hit |= pooled_max(mb, y, w + d) > 0.5f;
                        if (hit) { val = exp2f(-(float)d); break; }
                    }
                }
                g_dh[gt] = val;
            }
        } else {
            // F sum/sumsq chunk: 8192 float4 (128KB), 32 per thread, default
            // cache policy so L2 fills with F front-to-back. NO block
            // reduction here -- fold into thread-local doubles.
            long base = (long)(t - NT_IMG - NT_DT) * F_CHUNK + tid;
            float ps = 0.f, pq = 0.f;
            #pragma unroll 16
            for (int k = 0; k < F_CHUNK / TPB; k++) {
                float4 v = F[base + k * TPB];
                ps += (v.x + v.y) + (v.z + v.w);
                pq += (v.x * v.x + v.y * v.y) + (v.z * v.z + v.w * v.w);
            }
            ds += (double)ps;
            dq += (double)pq;
        }
    }
    // ONE block reduction for the whole phase
    s_s[tid] = ds;
    s_q[tid] = dq;
    __syncthreads();
    for (int off = 128; off > 0; off >>= 1) {
        if (tid < off) { s_s[tid] += s_s[tid + off]; s_q[tid] += s_q[tid + off]; }
        __syncthreads();
    }
    if (tid == 0) { g_ps[bid] = s_s[0]; g_pq[bid] = s_q[0]; }

    // ================ grid barrier (also resets ticket counters) ================
    grid_barrier_reset();

    // ---------------- Phase 2: every block folds the partials into stats
    {
        double ls = 0.0, lq = 0.0;
        for (int i = tid; i < GRID; i += TPB) { ls += g_ps[i]; lq += g_pq[i]; }
        s_s[tid] = ls; s_q[tid] = lq;
        __syncthreads();
        for (int off = 128; off > 0; off >>= 1) {
            if (tid < off) { s_s[tid] += s_s[tid + off]; s_q[tid] += s_q[tid + off]; }
            __syncthreads();
        }
        if (tid == 0) {
            double n = (double)NF;
            double mean = s_s[0] / n;
            double var = (s_q[0] - s_s[0] * s_s[0] / n) / (n - 1.0);
            double scale = 1.0 / sqrt(var * var + 1e-5);
            s_stats[0] = (float)(mean * scale);
            s_stats[1] = (float)scale;
        }
        __syncthreads();
    }

    const float ms = s_stats[0];
    const float sc = s_stats[1];

    // ---------------- Phase 3: fused epilogue, dynamic tickets in REVERSE
    // address order (ticket 0 -> highest F address = freshest in L2).
    // 1024 units of 32 channels: coefficient loads amortized over 32 streams.
    for (;;) {
        __syncthreads();
        if (tid == 0) s_t = atomicAdd(&g_t3, 1u);
        __syncthreads();
        unsigned int t = s_t;
        if (t >= NT3) break;

        const int v     = (NT3 - 1) - (int)t;
        const int chunk = v & 15;            // 16 pixel chunks of 1024
        const int cg    = (v >> 4) & 7;      // 8 channel-groups of 32
        const int b     = v >> 7;            // 0..7
        const int pix   = chunk * 1024 + tid * 4;

        const int sb = b * SP + pix;
        const int ib = b * 3 * SP + pix;

        float4 dh = *(const float4*)&g_dh[sb];
        float4 p0 = *(const float4*)&g_img_ds[ib];
        float4 p1 = *(const float4*)&g_img_ds[ib + SP];
        float4 p2 = *(const float4*)&g_img_ds[ib + 2 * SP];

        float q0[4] = { p0.x * dh.x, p0.y * dh.y, p0.z * dh.z, p0.w * dh.w };
        float q1[4] = { p1.x * dh.x, p1.y * dh.y, p1.z * dh.z, p1.w * dh.w };
        float q2[4] = { p2.x * dh.x, p2.y * dh.y, p2.z * dh.z, p2.w * dh.w };
        float q3[4] = { dh.x, dh.y, dh.z, dh.w };

        const int c0 = cg * 32;
        const float4* Fb = F   + (((size_t)(b * CF + c0) * SP + pix) >> 2);
        float4*       Ob = out + (((size_t)(b * CF + c0) * SP + pix) >> 2);
        const int cstride = SP >> 2;

        #pragma unroll 8
        for (int ci = 0; ci < 32; ci++) {
            float4 gwv = __ldg(&g_wpack[2 * (c0 + ci)]);
            float4 bwv = __ldg(&g_wpack[2 * (c0 + ci) + 1]);
            float4 f = __ldcs(&Fb[(size_t)ci * cstride]);
            float4 o;
            float gc, bc, fn;

            gc = fmaf(gwv.x, q0[0], fmaf(gwv.y, q1[0], fmaf(gwv.z, q2[0], gwv.w * q3[0])));
            bc = fmaf(bwv.x, q0[0], fmaf(bwv.y, q1[0], fmaf(bwv.z, q2[0], bwv.w * q3[0])));
            fn = fmaf(f.x, sc, -ms);
            o.x = fmaf(fn, gc, bc);

            gc = fmaf(gwv.x, q0[1], fmaf(gwv.y, q1[1], fmaf(gwv.z, q2[1], gwv.w * q3[1])));
            bc = fmaf(bwv.x, q0[1], fmaf(bwv.y, q1[1], fmaf(bwv.z, q2[1], bwv.w * q3[1])));
            fn = fmaf(f.y, sc, -ms);
            o.y = fmaf(fn, gc, bc);

            gc = fmaf(gwv.x, q0[2], fmaf(gwv.y, q1[2], fmaf(gwv.z, q2[2], gwv.w * q3[2])));
            bc = fmaf(bwv.x, q0[2], fmaf(bwv.y, q1[2], fmaf(bwv.z, q2[2], bwv.w * q3[2])));
            fn = fmaf(f.z, sc, -ms);
            o.z = fmaf(fn, gc, bc);

            gc = fmaf(gwv.x, q0[3], fmaf(gwv.y, q1[3], fmaf(gwv.z, q2[3], gwv.w * q3[3])));
            bc = fmaf(bwv.x, q0[3], fmaf(bwv.y, q1[3], fmaf(bwv.z, q2[3], bwv.w * q3[3])));
            fn = fmaf(f.w, sc, -ms);
            o.w = fmaf(fn, gc, bc);

            __stcs(&Ob[(size_t)ci * cstride], o);
        }
    }
}

// ---------------------------------------------------------------- launch
extern "C" void kernel_launch(void* const* d_in, const int* in_sizes, int n_in,
                              void* d_out, int out_size) {
    const float* F_in    = (const float*)d_in[0];
    const float* img_p   = (const float*)d_in[1];
    const float* mask    = (const float*)d_in[2];
    const float* gamma_w = (const float*)d_in[3];
    const float* gamma_b = (const float*)d_in[4];
    const float* beta_w  = (const float*)d_in[5];
    const float* beta_b  = (const float*)d_in[6];
    // d_in[7] = n_ds (==2), d_in[8] = n (==2): fixed by problem shapes.
    float* out = (float*)d_out;

    fused_kernel<<<GRID, TPB>>>((const float4*)F_in, img_p, mask,
                                gamma_w, gamma_b, beta_w, beta_b,
                                (float4*)out);
}

// round 8
// speedup vs baseline: 1.1398x; 1.1398x over previous
#include <cuda_runtime.h>
#include <math.h>

// Problem dims (fixed by setup_inputs)
#define BB   8
#define HH   512
#define WW   512
#define HP   128
#define WP   128
#define CF   256
#define SP   (HP*WP)            // 16384 spatial per plane
#define NF   (BB*CF*SP)         // 33554432 F_in elements
#define NV4  (NF/4)             // 8388608 float4s
#define GRID 592                // 148 SMs x 4 blocks: every SM exactly 4 resident
#define TPB  256
#define NTHREADS (GRID*TPB)     // 151552
#define F_ITERS  (NV4/NTHREADS) // 55
#define F_REM    (NV4 - F_ITERS*NTHREADS)  // 53248
// Phase-3: 4096 units (b, cg of 8ch, chunk of 1024px), static, reverse order
#define NT3  4096

// Device scratch (no allocations allowed). Partial slots overwritten every
// replay; g_bar is monotonic -> replay-safe.
__device__ double g_ps[GRID];
__device__ double g_pq[GRID];
__device__ float  g_img_ds[BB*3*SP];   // 4x4 avg-pooled img (1.5 MiB)
__device__ float  g_dh[BB*SP];         // distance-valued D_h
__device__ float4 g_wpack[2*CF];       // [2c]={gw0,gw1,gw2,gb}, [2c+1]={bw..}
__device__ unsigned int g_bar;         // monotonic ticket barrier

// ---------------------------------------------------------------- grid barrier
// Monotonic: correct across unlimited graph replays. Deadlock-free because
// all GRID blocks are simultaneously resident (592 = 148 SMs x 4 via bounds).
__device__ __forceinline__ void grid_barrier() {
    __syncthreads();
    if (threadIdx.x == 0) {
        __threadfence();
        unsigned int old = atomicAdd(&g_bar, 1u);
        unsigned int target = old - (old % GRID) + GRID;
        while (*((volatile unsigned int*)&g_bar) < target) __nanosleep(64);
        __threadfence();
    }
    __syncthreads();
}

// ---------------------------------------------------------------- on-the-fly 4x4 max-pool of raw mask
__device__ __forceinline__ float pooled_max(const float* __restrict__ mb, int h, int w) {
    const float* p = mb + (size_t)(h * 4) * WW + w * 4;
    float mx = 0.f;
    #pragma unroll
    for (int r = 0; r < 4; r++) {
        float4 v = __ldg((const float4*)(p + (size_t)r * WW));
        mx = fmaxf(mx, fmaxf(fmaxf(v.x, v.y), fmaxf(v.z, v.w)));
    }
    return mx;
}

// ---------------------------------------------------------------- the whole problem, one kernel
__global__ void __launch_bounds__(TPB, 4)
fused_kernel(const float4* __restrict__ F,
             const float*  __restrict__ img,
             const float*  __restrict__ mask,
             const float*  __restrict__ gw, const float* __restrict__ gB,
             const float*  __restrict__ bw, const float* __restrict__ bB,
             float4* __restrict__ out) {
    __shared__ double s_s[TPB];
    __shared__ double s_q[TPB];
    __shared__ float  s_stats[2];
    const int tid = threadIdx.x;
    const int bid = blockIdx.x;
    const int gt  = bid * TPB + tid;        // 0..151551

    // ---------------- Phase 1a: weight packing (first 256 global threads)
    if (gt < CF) {
        g_wpack[2*gt]     = make_float4(gw[3*gt], gw[3*gt+1], gw[3*gt+2], gB[gt]);
        g_wpack[2*gt + 1] = make_float4(bw[3*gt], bw[3*gt+1], bw[3*gt+2], bB[gt]);
    }

    // ---------------- Phase 1b: img 4x4 avg-pool (<=3 outputs per thread)
    // BEFORE the F sweep so these reads don't evict F's tail from L2.
    for (int idx = gt; idx < BB * 3 * SP; idx += NTHREADS) {
        int wp = idx & 127;
        int hp = (idx >> 7) & 127;
        int ch = (idx >> 14) % 3;
        int b  = idx / (3 * SP);
        const float* p = img + ((size_t)(b * 3 + ch) * HH + hp * 4) * WW + wp * 4;
        float s = 0.f;
        #pragma unroll
        for (int r = 0; r < 4; r++) {
            float4 v = __ldcs((const float4*)(p + (size_t)r * WW));
            s += (v.x + v.y) + (v.z + v.w);
        }
        g_img_ds[idx] = s * (1.f / 16.f);
    }

    // ---------------- Phase 1c: Chebyshev DT straight from the raw mask
    // 5 iters of (3x3 dilate -> 2^-i on newly reached) == per pooled pixel:
    //   d = Cheb dist to nearest pooled-1; value = (d<=5) ? 2^-d : 0
    if (gt < BB * SP) {
        int b   = gt >> 14;
        int rem = gt & 16383;
        int h = rem >> 7, w = rem & 127;
        const float* mb = mask + (size_t)b * 3 * HH * WW;   // channel 0
        float val;
        if (pooled_max(mb, h, w) > 0.5f) {
            val = 1.f;                                       // dominant path
        } else {
            val = 0.f;
            for (int d = 1; d <= 5; d++) {
                bool hit = false;
                int y0 = h - d, y1 = h + d;
                int xlo = w - d < 0 ? 0 : w - d;
                int xhi = w + d > WP - 1 ? WP - 1 : w + d;
                if (y0 >= 0) for (int x = xlo; x <= xhi; x++) hit |= pooled_max(mb, y0, x) > 0.5f;
                if (y1 < HP) for (int x = xlo; x <= xhi; x++) hit |= pooled_max(mb, y1, x) > 0.5f;
                int ylo = h - d + 1 < 0 ? 0 : h - d + 1;
                int yhi = h + d - 1 > HP - 1 ? HP - 1 : h + d - 1;
                if (w - d >= 0) for (int y = ylo; y <= yhi; y++) hit |= pooled_max(mb, y, w - d) > 0.5f;
                if (w + d < WP) for (int y = ylo; y <= yhi; y++) hit |= pooled_max(mb, y, w + d) > 0.5f;
                if (hit) { val = exp2f(-(float)d); break; }
            }
        }
        g_dh[gt] = val;
    }

    // ---------------- Phase 1d: F sum/sumsq, DEFAULT cache policy.
    // Interleaved grid-stride: whole chip sweeps F front-to-back together, so
    // at the end L2 (~126MB) holds F's TAIL. Phase 3 walks backwards into it.
    {
        float ps = 0.f, pq = 0.f;
        #pragma unroll 11
        for (int k = 0; k < F_ITERS; k++) {
            float4 v = F[(long)gt + (long)k * NTHREADS];
            ps += (v.x + v.y) + (v.z + v.w);
            pq += (v.x * v.x + v.y * v.y) + (v.z * v.z + v.w * v.w);
        }
        if (gt < F_REM) {
            float4 v = F[(long)gt + (long)F_ITERS * NTHREADS];
            ps += (v.x + v.y) + (v.z + v.w);
            pq += (v.x * v.x + v.y * v.y) + (v.z * v.z + v.w * v.w);
        }
        s_s[tid] = (double)ps;
        s_q[tid] = (double)pq;
        __syncthreads();
        for (int off = 128; off > 0; off >>= 1) {
            if (tid < off) { s_s[tid] += s_s[tid + off]; s_q[tid] += s_q[tid + off]; }
            __syncthreads();
        }
        if (tid == 0) { g_ps[bid] = s_s[0]; g_pq[bid] = s_q[0]; }
    }

    // ================ the one grid-wide barrier ================
    grid_barrier();

    // ---------------- Phase 2: every block folds the partials into stats
    {
        double ls = 0.0, lq = 0.0;
        for (int i = tid; i < GRID; i += TPB) { ls += g_ps[i]; lq += g_pq[i]; }
        s_s[tid] = ls; s_q[tid] = lq;
        __syncthreads();
        for (int off = 128; off > 0; off >>= 1) {
            if (tid < off) { s_s[tid] += s_s[tid + off]; s_q[tid] += s_q[tid + off]; }
            __syncthreads();
        }
        if (tid == 0) {
            double n = (double)NF;
            double mean = s_s[0] / n;
            double var = (s_q[0] - s_s[0] * s_s[0] / n) / (n - 1.0);
            double scale = 1.0 / sqrt(var * var + 1e-5);
            s_stats[0] = (float)(mean * scale);
            s_stats[1] = (float)scale;
        }
        __syncthreads();
    }

    const float ms = s_stats[0];
    const float sc = s_stats[1];

    // ---------------- Phase 3: fused epilogue. 4096 static units of 8
    // channels x 1024 pixels, walked in REVERSE address order (first-touched
    // = highest F address = freshest in L2 from phase 1d). 7 or 6 units per
    // block -> ~1% straggle.
    for (int k = 0; ; k++) {
        const int uid = k * GRID + bid;
        if (uid >= NT3) break;
        const int v     = (NT3 - 1) - uid;
        const int chunk = v & 15;            // 16 pixel chunks of 1024
        const int cg    = (v >> 4) & 31;     // 32 channel-groups of 8
        const int b     = v >> 9;            // 0..7
        const int pix   = chunk * 1024 + tid * 4;

        const int sb = b * SP + pix;
        const int ib = b * 3 * SP + pix;

        float4 dh = *(const float4*)&g_dh[sb];
        float4 p0 = *(const float4*)&g_img_ds[ib];
        float4 p1 = *(const float4*)&g_img_ds[ib + SP];
        float4 p2 = *(const float4*)&g_img_ds[ib + 2 * SP];

        float q0[4] = { p0.x * dh.x, p0.y * dh.y, p0.z * dh.z, p0.w * dh.w };
        float q1[4] = { p1.x * dh.x, p1.y * dh.y, p1.z * dh.z, p1.w * dh.w };
        float q2[4] = { p2.x * dh.x, p2.y * dh.y, p2.z * dh.z, p2.w * dh.w };
        float q3[4] = { dh.x, dh.y, dh.z, dh.w };

        const int c0 = cg * 8;
        const float4* Fb = F   + (((size_t)(b * CF + c0) * SP + pix) >> 2);
        float4*       Ob = out + (((size_t)(b * CF + c0) * SP + pix) >> 2);
        const int cstride = SP >> 2;

        #pragma unroll
        for (int ci = 0; ci < 8; ci++) {
            float4 gwv = __ldg(&g_wpack[2 * (c0 + ci)]);
            float4 bwv = __ldg(&g_wpack[2 * (c0 + ci) + 1]);
            float4 f = __ldcs(&Fb[(size_t)ci * cstride]);
            float4 o;
            float gc, bc, fn;

            gc = fmaf(gwv.x, q0[0], fmaf(gwv.y, q1[0], fmaf(gwv.z, q2[0], gwv.w * q3[0])));
            bc = fmaf(bwv.x, q0[0], fmaf(bwv.y, q1[0], fmaf(bwv.z, q2[0], bwv.w * q3[0])));
            fn = fmaf(f.x, sc, -ms);
            o.x = fmaf(fn, gc, bc);

            gc = fmaf(gwv.x, q0[1], fmaf(gwv.y, q1[1], fmaf(gwv.z, q2[1], gwv.w * q3[1])));
            bc = fmaf(bwv.x, q0[1], fmaf(bwv.y, q1[1], fmaf(bwv.z, q2[1], bwv.w * q3[1])));
            fn = fmaf(f.y, sc, -ms);
            o.y = fmaf(fn, gc, bc);

            gc = fmaf(gwv.x, q0[2], fmaf(gwv.y, q1[2], fmaf(gwv.z, q2[2], gwv.w * q3[2])));
            bc = fmaf(bwv.x, q0[2], fmaf(bwv.y, q1[2], fmaf(bwv.z, q2[2], bwv.w * q3[2])));
            fn = fmaf(f.z, sc, -ms);
            o.z = fmaf(fn, gc, bc);

            gc = fmaf(gwv.x, q0[3], fmaf(gwv.y, q1[3], fmaf(gwv.z, q2[3], gwv.w * q3[3])));
            bc = fmaf(bwv.x, q0[3], fmaf(bwv.y, q1[3], fmaf(bwv.z, q2[3], bwv.w * q3[3])));
            fn = fmaf(f.w, sc, -ms);
            o.w = fmaf(fn, gc, bc);

            __stcs(&Ob[(size_t)ci * cstride], o);
        }
    }
}

// ---------------------------------------------------------------- launch
extern "C" void kernel_launch(void* const* d_in, const int* in_sizes, int n_in,
                              void* d_out, int out_size) {
    const float* F_in    = (const float*)d_in[0];
    const float* img_p   = (const float*)d_in[1];
    const float* mask    = (const float*)d_in[2];
    const float* gamma_w = (const float*)d_in[3];
    const float* gamma_b = (const float*)d_in[4];
    const float* beta_w  = (const float*)d_in[5];
    const float* beta_b  = (const float*)d_in[6];
    // d_in[7] = n_ds (==2), d_in[8] = n (==2): fixed by problem shapes.
    float* out = (float*)d_out;

    fused_kernel<<<GRID, TPB>>>((const float4*)F_in, img_p, mask,
                                gamma_w, gamma_b, beta_w, beta_b,
                                (float4*)out);
}